// round 7
// baseline (speedup 1.0000x reference)
#include <cuda_runtime.h>
#include <cuda_fp16.h>
#include <math.h>

#define Bb 4
#define Nn 20000
#define Uu 64
#define Ff 65
#define Ee 640000
#define NODES (Bb*Nn)
#define ATT_SCALE 0.125f
#define FP 68          // padded weight row stride (floats)
#define XS 36          // f-major x row stride (32 nodes + pad)
#define NCHUNK (NODES/32)   // 2500

typedef unsigned long long ull;

__device__ __forceinline__ ull pack2(float v) {
    ull r; asm("mov.b64 %0, {%1, %1};" : "=l"(r) : "f"(v)); return r;
}
__device__ __forceinline__ void fma2(ull &acc, ull x, ull w) {
    asm("fma.rn.f32x2 %0, %1, %2, %0;" : "+l"(acc) : "l"(x), "l"(w));
}
__device__ __forceinline__ float2 unpack2(ull v) {
    float2 f; asm("mov.b64 {%0, %1}, %2;" : "=f"(f.x), "=f"(f.y) : "l"(v)); return f;
}

// ---------------- device scratch (static, no runtime alloc) ----------------
__device__ __align__(16) __half g_qh[NODES*Uu];   // prescaled by ATT_SCALE
__device__ __align__(16) __half g_kh[NODES*Uu];
__device__ __align__(16) __half g_vh[NODES*Uu];
__device__ __align__(16) float  g_agg[NODES*Uu];  // agg, then h2 in-place
__device__ unsigned char g_mask[NODES];
__device__ int g_cnt[Nn];
__device__ int g_off[Nn];
__device__ int g_cur[Nn];
__device__ int g_srt[Ee];   // src ids sorted by dst (CSR payload)

// ---------------- CSR build ----------------
__global__ void hist_kernel(const int* __restrict__ edst) {
    int i = blockIdx.x * blockDim.x + threadIdx.x;
    if (i < Ee/4) {
        int4 d = ((const int4*)edst)[i];
        atomicAdd(&g_cnt[d.x], 1);
        atomicAdd(&g_cnt[d.y], 1);
        atomicAdd(&g_cnt[d.z], 1);
        atomicAdd(&g_cnt[d.w], 1);
    }
}

__global__ void scan_kernel() {
    __shared__ int sp[1024];
    int tid = threadIdx.x;
    int base = tid * 20;
    int s = 0;
    #pragma unroll
    for (int i = 0; i < 20; i++) {
        int idx = base + i;
        if (idx < Nn) s += g_cnt[idx];
    }
    sp[tid] = s;
    __syncthreads();
    for (int d = 1; d < 1024; d <<= 1) {
        int v = (tid >= d) ? sp[tid - d] : 0;
        __syncthreads();
        sp[tid] += v;
        __syncthreads();
    }
    int run = sp[tid] - s;   // exclusive prefix
    #pragma unroll
    for (int i = 0; i < 20; i++) {
        int idx = base + i;
        if (idx < Nn) {
            g_off[idx] = run;
            g_cur[idx] = run;
            run += g_cnt[idx];
        }
    }
}

__global__ void scatter_kernel(const int* __restrict__ edst,
                               const int* __restrict__ esrc) {
    int i = blockIdx.x * blockDim.x + threadIdx.x;
    if (i < Ee/4) {
        int4 d = ((const int4*)edst)[i];
        int4 s = ((const int4*)esrc)[i];
        int p0 = atomicAdd(&g_cur[d.x], 1); g_srt[p0] = s.x;
        int p1 = atomicAdd(&g_cur[d.y], 1); g_srt[p1] = s.y;
        int p2 = atomicAdd(&g_cur[d.z], 1); g_srt[p2] = s.z;
        int p3 = atomicAdd(&g_cur[d.w], 1); g_srt[p3] = s.w;
    }
}

// ---------------- QKV projection: one matrix per CTA (m = blockIdx%3) ------
__global__ void __launch_bounds__(256) qkv_kernel(
    const float* __restrict__ inputs, const float* __restrict__ state,
    const float* __restrict__ Wq, const float* __restrict__ bq,
    const float* __restrict__ Wk, const float* __restrict__ bk,
    const float* __restrict__ Wv, const float* __restrict__ bv)
{
    extern __shared__ float sm[];
    float* sWT = sm;                   // 64*FP   (W[u][f], zero-padded f=65..67)
    float* sb  = sWT + 64*FP;          // 64
    float* sxT = sb + 64;              // 68*XS   (x[f][node], 32 nodes)

    int m = blockIdx.x % 3;
    const float* W  = (m == 0) ? Wq : (m == 1) ? Wk : Wv;
    const float* bb = (m == 0) ? bq : (m == 1) ? bk : bv;
    __half* dst = (m == 0) ? g_qh : (m == 1) ? g_kh : g_vh;
    float scale = (m == 0) ? ATT_SCALE : 1.f;

    for (int i = threadIdx.x; i < Ff*Uu; i += 256) {
        int f = i >> 6, u = i & 63;
        sWT[u*FP + f] = W[i];
    }
    for (int i = threadIdx.x; i < 192; i += 256) {
        int u = i & 63, p = i >> 6;    // pad f=65..67
        sWT[u*FP + 65 + p] = 0.f;
    }
    if (threadIdx.x < 64) sb[threadIdx.x] = bb[threadIdx.x];
    if (threadIdx.x < 96) {            // zero pad rows 65..67 once
        int r = 65 + threadIdx.x / 32;
        sxT[r*XS + (threadIdx.x & 31)] = 0.f;
    }
    __syncthreads();

    int u = threadIdx.x & 63;
    int g = threadIdx.x >> 6;
    int ln0 = g * 8;
    const float4* w4 = (const float4*)(sWT + u*FP);
    int cstep = gridDim.x / 3;

    for (int c = blockIdx.x / 3; c < NCHUNK; c += cstep) {
        int base = c * 32;
        __syncthreads();
        #pragma unroll
        for (int i = threadIdx.x; i < 512; i += 256) {
            int node = i >> 4, f4 = i & 15;
            float4 v = ((const float4*)state)[(size_t)(base + node)*16 + f4];
            sxT[(f4*4+0)*XS + node] = v.x;
            sxT[(f4*4+1)*XS + node] = v.y;
            sxT[(f4*4+2)*XS + node] = v.z;
            sxT[(f4*4+3)*XS + node] = v.w;
        }
        if (threadIdx.x < 32) {
            int node = base + threadIdx.x;
            sxT[64*XS + threadIdx.x] = inputs[node];
            if (m == 0)
                g_mask[node] = (__ldg(&state[(size_t)node*Uu + 58]) != 0.f) ? 1 : 0;
        }
        __syncthreads();

        ull a[4];
        #pragma unroll
        for (int p = 0; p < 4; p++) a[p] = 0ull;

        #pragma unroll 4
        for (int f4 = 0; f4 < 17; f4++) {
            float4 w = w4[f4];
            #pragma unroll
            for (int e = 0; e < 4; e++) {
                int f = f4*4 + e;
                ulonglong2 xab = *(const ulonglong2*)(sxT + f*XS + ln0);
                ulonglong2 xcd = *(const ulonglong2*)(sxT + f*XS + ln0 + 4);
                float we = (e==0)?w.x:(e==1)?w.y:(e==2)?w.z:w.w;
                ull w2 = pack2(we);
                fma2(a[0], xab.x, w2); fma2(a[1], xab.y, w2);
                fma2(a[2], xcd.x, w2); fma2(a[3], xcd.y, w2);
            }
        }
        float bv_ = sb[u];
        #pragma unroll
        for (int p = 0; p < 4; p++) {
            float2 f2 = unpack2(a[p]);
            size_t i0 = (size_t)(base + ln0 + 2*p)*Uu + u;
            dst[i0]      = __float2half_rn((f2.x + bv_) * scale);
            dst[i0 + Uu] = __float2half_rn((f2.y + bv_) * scale);
        }
    }
}

// ---------------- attention: one warp per (b, dst), 8 lanes per edge -------
__device__ __forceinline__ void ld_h8(const __half* p, float2 f[4]) {
    uint4 r = *reinterpret_cast<const uint4*>(p);
    f[0] = __half22float2(*reinterpret_cast<__half2*>(&r.x));
    f[1] = __half22float2(*reinterpret_cast<__half2*>(&r.y));
    f[2] = __half22float2(*reinterpret_cast<__half2*>(&r.z));
    f[3] = __half22float2(*reinterpret_cast<__half2*>(&r.w));
}

__global__ void __launch_bounds__(256) attn_kernel() {
    int gw = (blockIdx.x * blockDim.x + threadIdx.x) >> 5;
    if (gw >= NODES) return;
    if (!g_mask[gw]) return;

    int lane = threadIdx.x & 31;
    int grp  = lane >> 3;     // edge slot 0..3
    int sub  = lane & 7;      // dim group: dims [sub*8, sub*8+8)
    int b = gw / Nn;
    int n = gw - b * Nn;

    size_t rowbase = (size_t)gw * Uu;
    float2 q[4];
    ld_h8(g_qh + rowbase + sub*8, q);

    int off = g_off[n];
    int deg = g_cnt[n];
    int end = off + deg;
    const __half* kb = g_kh + (size_t)b * Nn * Uu;
    const __half* vb = g_vh + (size_t)b * Nn * Uu;
    const unsigned char* mk = g_mask + b * Nn;

    float2 acc[4] = {{0,0},{0,0},{0,0},{0,0}};
    float den = 0.f;

    // prefetch first src ids
    int sA = 0, sB = 0; bool vA = false, vB = false;
    if (off < end) {
        int eA = off + grp, eB = off + 4 + grp;
        vA = eA < end; vB = eB < end;
        sA = __ldg(&g_srt[vA ? eA : off]);
        sB = __ldg(&g_srt[vB ? eB : off]);
    }

    for (int t = off; t < end; t += 8) {
        int s0 = sA, s1 = sB;
        bool val0 = vA, val1 = vB;
        int tn = t + 8;
        if (tn < end) {          // prefetch next iteration's src ids
            int eA = tn + grp, eB = tn + 4 + grp;
            vA = eA < end; vB = eB < end;
            sA = __ldg(&g_srt[vA ? eA : off]);
            sB = __ldg(&g_srt[vB ? eB : off]);
        }

        // issue all loads up-front (mask, k, v)
        unsigned m0 = mk[s0], m1 = mk[s1];
        float2 k0[4], k1[4], v0[4], v1[4];
        ld_h8(kb + (size_t)s0 * Uu + sub*8, k0);
        ld_h8(kb + (size_t)s1 * Uu + sub*8, k1);
        ld_h8(vb + (size_t)s0 * Uu + sub*8, v0);
        ld_h8(vb + (size_t)s1 * Uu + sub*8, v1);

        float p0 = k0[0].x*q[0].x + k0[0].y*q[0].y
                 + k0[1].x*q[1].x + k0[1].y*q[1].y
                 + k0[2].x*q[2].x + k0[2].y*q[2].y
                 + k0[3].x*q[3].x + k0[3].y*q[3].y;
        float p1 = k1[0].x*q[0].x + k1[0].y*q[0].y
                 + k1[1].x*q[1].x + k1[1].y*q[1].y
                 + k1[2].x*q[2].x + k1[2].y*q[2].y
                 + k1[3].x*q[3].x + k1[3].y*q[3].y;
        #pragma unroll
        for (int d = 1; d < 8; d <<= 1) {
            p0 += __shfl_xor_sync(0xffffffffu, p0, d);
            p1 += __shfl_xor_sync(0xffffffffu, p1, d);
        }
        float w0 = (val0 && m0) ? __expf(p0) : 0.f;
        float w1 = (val1 && m1) ? __expf(p1) : 0.f;

        #pragma unroll
        for (int i = 0; i < 4; i++) {
            acc[i].x += w0 * v0[i].x + w1 * v1[i].x;
            acc[i].y += w0 * v0[i].y + w1 * v1[i].y;
        }
        den += w0 + w1;
    }

    // cross-group reduce (groups 0..3 hold disjoint edge subsets)
    #pragma unroll
    for (int d = 8; d < 32; d <<= 1) {
        #pragma unroll
        for (int i = 0; i < 4; i++) {
            acc[i].x += __shfl_xor_sync(0xffffffffu, acc[i].x, d);
            acc[i].y += __shfl_xor_sync(0xffffffffu, acc[i].y, d);
        }
        den += __shfl_xor_sync(0xffffffffu, den, d);
    }

    if (lane < 8) {
        float inv = (den > 0.f) ? 1.f / fmaxf(den, 1e-16f) : 0.f;
        float4* op = (float4*)(g_agg + rowbase + sub * 8);
        op[0] = make_float4(acc[0].x*inv, acc[0].y*inv, acc[1].x*inv, acc[1].y*inv);
        op[1] = make_float4(acc[2].x*inv, acc[2].y*inv, acc[3].x*inv, acc[3].y*inv);
    }
}

// ---------------- gru_a: h2 = mask ? agg + x@Ws + bs : h  (in-place g_agg) --
__global__ void __launch_bounds__(256) gru_a_kernel(
    const float* __restrict__ inputs, const float* __restrict__ state,
    const float* __restrict__ Ws, const float* __restrict__ bs)
{
    extern __shared__ float sm[];
    float* sWT = sm;                   // 64*FP
    float* sbs = sWT + 64*FP;          // 64
    float* sxT = sbs + 64;             // 68*XS

    for (int i = threadIdx.x; i < Ff*Uu; i += 256) {
        int f = i >> 6, u = i & 63;
        sWT[u*FP + f] = Ws[i];
    }
    for (int i = threadIdx.x; i < 192; i += 256) {
        int u = i & 63, p = i >> 6;
        sWT[u*FP + 65 + p] = 0.f;
    }
    if (threadIdx.x < 64) sbs[threadIdx.x] = bs[threadIdx.x];
    if (threadIdx.x < 96) {
        int r = 65 + threadIdx.x / 32;
        sxT[r*XS + (threadIdx.x & 31)] = 0.f;
    }
    __syncthreads();

    int u = threadIdx.x & 63;
    int g = threadIdx.x >> 6;
    int ln0 = g * 8;
    const float4* w4 = (const float4*)(sWT + u*FP);

    for (int c = blockIdx.x; c < NCHUNK; c += gridDim.x) {
        int base = c * 32;
        __syncthreads();
        #pragma unroll
        for (int i = threadIdx.x; i < 512; i += 256) {
            int node = i >> 4, f4 = i & 15;
            float4 v = ((const float4*)state)[(size_t)(base + node)*16 + f4];
            sxT[(f4*4+0)*XS + node] = v.x;
            sxT[(f4*4+1)*XS + node] = v.y;
            sxT[(f4*4+2)*XS + node] = v.z;
            sxT[(f4*4+3)*XS + node] = v.w;
        }
        if (threadIdx.x < 32) {
            sxT[64*XS + threadIdx.x] = inputs[base + threadIdx.x];
        }
        __syncthreads();

        ull a[4];
        #pragma unroll
        for (int p = 0; p < 4; p++) a[p] = 0ull;
        #pragma unroll 4
        for (int f4 = 0; f4 < 17; f4++) {
            float4 w = w4[f4];
            #pragma unroll
            for (int e = 0; e < 4; e++) {
                int f = f4*4 + e;
                ulonglong2 xab = *(const ulonglong2*)(sxT + f*XS + ln0);
                ulonglong2 xcd = *(const ulonglong2*)(sxT + f*XS + ln0 + 4);
                float we = (e==0)?w.x:(e==1)?w.y:(e==2)?w.z:w.w;
                ull w2 = pack2(we);
                fma2(a[0], xab.x, w2); fma2(a[1], xab.y, w2);
                fma2(a[2], xcd.x, w2); fma2(a[3], xcd.y, w2);
            }
        }
        float bsu = sbs[u];
        #pragma unroll
        for (int p = 0; p < 4; p++) {
            float2 f2 = unpack2(a[p]);
            #pragma unroll
            for (int q = 0; q < 2; q++) {
                int nl = ln0 + 2*p + q;
                int node = base + nl;
                float sres = q ? f2.y : f2.x;
                float hv  = sxT[u*XS + nl];
                bool msk  = (sxT[58*XS + nl] != 0.f);
                size_t gi = (size_t)node*Uu + u;
                float av  = g_agg[gi];
                g_agg[gi] = msk ? (av + sres + bsu) : hv;   // h2 in place
            }
        }
    }
}

// ---------------- gru_b: gates + output ----------------
__global__ void __launch_bounds__(256) gru_b_kernel(
    const float* __restrict__ inputs,
    const float* __restrict__ W1, const float* __restrict__ b1,
    const float* __restrict__ W2, const float* __restrict__ b2,
    float* __restrict__ out)
{
    extern __shared__ float sm[];
    float* sW1aT = sm;                   // cols 0..63 (reset)
    float* sW1bT = sW1aT + 64*FP;        // cols 64..127 (z)
    float* sW2T  = sW1bT + 64*FP;
    float* sb1 = sW2T + 64*FP;           // 128
    float* sb2 = sb1 + 128;              // 64
    float* shT = sb2 + 64;               // 68*XS: row0 = xin, rows1..64 = h2

    for (int i = threadIdx.x; i < Ff*Uu; i += 256) {
        int f = i >> 6, u = i & 63;
        sW2T[u*FP + f] = W2[i];
    }
    for (int i = threadIdx.x; i < Ff*128; i += 256) {
        int f = i >> 7, c = i & 127;
        if (c < 64) sW1aT[c*FP + f] = W1[i];
        else        sW1bT[(c-64)*FP + f] = W1[i];
    }
    for (int i = threadIdx.x; i < 192; i += 256) {
        int u = i & 63, p = i >> 6;
        sW1aT[u*FP + 65 + p] = 0.f;
        sW1bT[u*FP + 65 + p] = 0.f;
        sW2T[u*FP + 65 + p] = 0.f;
    }
    if (threadIdx.x < 128) sb1[threadIdx.x] = b1[threadIdx.x];
    if (threadIdx.x < 64)  sb2[threadIdx.x] = b2[threadIdx.x];
    if (threadIdx.x < 96) {              // zero pad rows 65..67
        int r = 65 + threadIdx.x / 32;
        shT[r*XS + (threadIdx.x & 31)] = 0.f;
    }
    __syncthreads();

    int u = threadIdx.x & 63;
    int g = threadIdx.x >> 6;
    int ln0 = g * 8;
    const float4* w1a4 = (const float4*)(sW1aT + u*FP);
    const float4* w1b4 = (const float4*)(sW1bT + u*FP);
    const float4* w24  = (const float4*)(sW2T  + u*FP);

    for (int c = blockIdx.x; c < NCHUNK; c += gridDim.x) {
        int base = c * 32;
        __syncthreads();
        // stage h2 (from g_agg) into rows 1..64; xin into row 0
        #pragma unroll
        for (int i = threadIdx.x; i < 512; i += 256) {
            int node = i >> 4, f4 = i & 15;
            float4 v = ((const float4*)g_agg)[(size_t)(base + node)*16 + f4];
            shT[(f4*4+1)*XS + node] = v.x;
            shT[(f4*4+2)*XS + node] = v.y;
            shT[(f4*4+3)*XS + node] = v.z;
            shT[(f4*4+4)*XS + node] = v.w;
        }
        if (threadIdx.x < 32) {
            shT[threadIdx.x] = inputs[base + threadIdx.x];
        }
        __syncthreads();

        // gates: a1 (reset), a2 (z) = [xin, h2] @ W1 + b1
        ull a1[4], a2[4];
        ull b1a = pack2(sb1[u]), b1b = pack2(sb1[64+u]);
        #pragma unroll
        for (int p = 0; p < 4; p++) { a1[p] = b1a; a2[p] = b1b; }
        #pragma unroll 4
        for (int f4 = 0; f4 < 17; f4++) {
            float4 wa = w1a4[f4], wb = w1b4[f4];
            #pragma unroll
            for (int e = 0; e < 4; e++) {
                int f = f4*4 + e;
                ulonglong2 xab = *(const ulonglong2*)(shT + f*XS + ln0);
                ulonglong2 xcd = *(const ulonglong2*)(shT + f*XS + ln0 + 4);
                float wae = (e==0)?wa.x:(e==1)?wa.y:(e==2)?wa.z:wa.w;
                float wbe = (e==0)?wb.x:(e==1)?wb.y:(e==2)?wb.z:wb.w;
                ull wa2 = pack2(wae), wb2 = pack2(wbe);
                fma2(a1[0], xab.x, wa2); fma2(a1[1], xab.y, wa2);
                fma2(a1[2], xcd.x, wa2); fma2(a1[3], xcd.y, wa2);
                fma2(a2[0], xab.x, wb2); fma2(a2[1], xab.y, wb2);
                fma2(a2[2], xcd.x, wb2); fma2(a2[3], xcd.y, wb2);
            }
        }
        float zz[8], rst[8], h2v[8];
        #pragma unroll
        for (int p = 0; p < 4; p++) {
            float2 f1 = unpack2(a1[p]);
            float2 f2 = unpack2(a2[p]);
            rst[2*p]   = 1.f / (1.f + __expf(-f1.x));
            rst[2*p+1] = 1.f / (1.f + __expf(-f1.y));
            zz[2*p]    = 1.f / (1.f + __expf(-f2.x));
            zz[2*p+1]  = 1.f / (1.f + __expf(-f2.y));
        }
        #pragma unroll
        for (int j = 0; j < 8; j++)
            h2v[j] = shT[(1+u)*XS + ln0 + j];
        __syncthreads();     // all gate reads of shT complete

        // overwrite rows 1..64 with reset*h2 (row 0 = xin unchanged)
        #pragma unroll
        for (int j = 0; j < 8; j++)
            shT[(1+u)*XS + ln0 + j] = rst[j] * h2v[j];
        __syncthreads();

        // c = tanh([xin, reset*h2] @ W2 + b2); out = (1-z) h2 + z c
        ull cacc[4];
        ull b2p = pack2(sb2[u]);
        #pragma unroll
        for (int p = 0; p < 4; p++) cacc[p] = b2p;
        #pragma unroll 4
        for (int f4 = 0; f4 < 17; f4++) {
            float4 w = w24[f4];
            #pragma unroll
            for (int e = 0; e < 4; e++) {
                int f = f4*4 + e;
                ulonglong2 xab = *(const ulonglong2*)(shT + f*XS + ln0);
                ulonglong2 xcd = *(const ulonglong2*)(shT + f*XS + ln0 + 4);
                float we = (e==0)?w.x:(e==1)?w.y:(e==2)?w.z:w.w;
                ull w2 = pack2(we);
                fma2(cacc[0], xab.x, w2); fma2(cacc[1], xab.y, w2);
                fma2(cacc[2], xcd.x, w2); fma2(cacc[3], xcd.y, w2);
            }
        }
        #pragma unroll
        for (int p = 0; p < 4; p++) {
            float2 f2 = unpack2(cacc[p]);
            int j0 = 2*p;
            float cc0 = tanhf(f2.x), cc1 = tanhf(f2.y);
            size_t i0 = (size_t)(base + ln0 + j0)*Uu + u;
            out[i0]      = (1.f - zz[j0])   * h2v[j0]   + zz[j0]   * cc0;
            out[i0 + Uu] = (1.f - zz[j0+1]) * h2v[j0+1] + zz[j0+1] * cc1;
        }
    }
}

// ---------------- launch ----------------
extern "C" void kernel_launch(void* const* d_in, const int* in_sizes, int n_in,
                              void* d_out, int out_size)
{
    const float* inputs = (const float*)d_in[0];
    const float* state  = (const float*)d_in[1];
    const int*   esrc   = (const int*)d_in[2];
    const int*   edst   = (const int*)d_in[3];
    const float* Wq = (const float*)d_in[4];
    const float* bq = (const float*)d_in[5];
    const float* Wk = (const float*)d_in[6];
    const float* bk = (const float*)d_in[7];
    const float* Wv = (const float*)d_in[8];
    const float* bv = (const float*)d_in[9];
    const float* Ws = (const float*)d_in[10];
    const float* bs = (const float*)d_in[11];
    const float* W1 = (const float*)d_in[12];
    const float* b1 = (const float*)d_in[13];
    const float* W2 = (const float*)d_in[14];
    const float* b2 = (const float*)d_in[15];
    float* out = (float*)d_out;

    const int SMEM_Q = (64*FP + 64 + 68*XS) * (int)sizeof(float);
    const int SMEM_A = (64*FP + 64 + 68*XS) * (int)sizeof(float);
    const int SMEM_B = (3*64*FP + 192 + 68*XS) * (int)sizeof(float);

    cudaFuncSetAttribute(qkv_kernel,   cudaFuncAttributeMaxDynamicSharedMemorySize, SMEM_Q);
    cudaFuncSetAttribute(gru_a_kernel, cudaFuncAttributeMaxDynamicSharedMemorySize, SMEM_A);
    cudaFuncSetAttribute(gru_b_kernel, cudaFuncAttributeMaxDynamicSharedMemorySize, SMEM_B);

    // CSR build (counts zeroed by async memset; graph-capturable, no alloc)
    void* cnt_ptr = nullptr;
    cudaGetSymbolAddress(&cnt_ptr, g_cnt);
    cudaMemsetAsync(cnt_ptr, 0, Nn * sizeof(int), 0);
    hist_kernel<<<(Ee/4 + 255)/256, 256>>>(edst);
    scan_kernel<<<1, 1024>>>();
    scatter_kernel<<<(Ee/4 + 255)/256, 256>>>(edst, esrc);

    // projections: one matrix per CTA (blockIdx % 3)
    qkv_kernel<<<1332, 256, SMEM_Q>>>(inputs, state, Wq, bq, Wk, bk, Wv, bv);

    // attention: one warp per (b, dst)
    attn_kernel<<<(NODES*32 + 255)/256, 256>>>();

    // GRU: h2 in-place into g_agg, then gates + output
    gru_a_kernel<<<1184, 256, SMEM_A>>>(inputs, state, Ws, bs);
    gru_b_kernel<<<444, 256, SMEM_B>>>(inputs, W1, b1, W2, b2, out);
}